// round 3
// baseline (speedup 1.0000x reference)
#include <cuda_runtime.h>

#define N_SENT   2048
#define SEQ_L    128
#define D        256
#define C        64
#define NUM_BAGS 128
#define BAG      16

// Scratch (device globals — no allocation allowed)
__device__ float g_v[C * D];          // v_q = A_q @ rq_q
__device__ float g_u[C * D];          // u_q = attW_q * relW_q
__device__ float g_xpool[N_SENT * D]; // per-sentence pooled vectors
__device__ float g_logit[N_SENT];    // per-sentence bag-attention logits
__device__ int   g_qstride;          // 1 if attention_query is int32, 2 if int64

// --------------------------------------------------------------------------
// Kernel 0: detect int32 vs int64 layout of attention_query.
// If the data is little-endian int64 (values 0..63), every odd 32-bit word in
// the first 2048 words is the zero high-half. If int32, odd words are random
// class ids (P(all zero) ~ 64^-1024). Stays in-bounds either way.
// --------------------------------------------------------------------------
__global__ void detect_kernel(const int* __restrict__ aq) {
    __shared__ int s_any;
    if (threadIdx.x == 0) s_any = 0;
    __syncthreads();
    int local = 0;
    for (int t = threadIdx.x; t < N_SENT / 2; t += blockDim.x)
        local |= aq[2 * t + 1];
    if (local) atomicOr(&s_any, 1);
    __syncthreads();
    if (threadIdx.x == 0) g_qstride = s_any ? 1 : 2;
}

// --------------------------------------------------------------------------
// Kernel 1: u_q[d] = attention_W[q][d] * relation_W[q][d]
// --------------------------------------------------------------------------
__global__ void pre_u_kernel(const float* __restrict__ relW,
                             const float* __restrict__ attW) {
    int i = blockIdx.x * D + threadIdx.x;
    g_u[i] = relW[i] * attW[i];
}

// --------------------------------------------------------------------------
// Kernel 2: v_q[d] = sum_e assemble_W[q][d*D + e] * relation_W[q][e]
// grid = C*32 blocks of 256 threads; each warp handles one row d (coalesced
// float4 reads of the 64 MiB assemble_W, read exactly once).
// --------------------------------------------------------------------------
__global__ __launch_bounds__(256) void pre_v_kernel(
    const float* __restrict__ asmW, const float* __restrict__ relW) {
    int b    = blockIdx.x;
    int q    = b >> 5;                       // 32 blocks per class
    int warp = threadIdx.x >> 5;
    int lane = threadIdx.x & 31;
    int d    = ((b & 31) << 3) + warp;       // 8 rows per block

    const float4* arow = (const float4*)(asmW + (size_t)q * (D * D) + (size_t)d * D);
    const float4* rq4  = (const float4*)(relW + q * D);

    float4 a0 = arow[lane],      a1 = arow[lane + 32];
    float4 r0 = rq4[lane],       r1 = rq4[lane + 32];
    float s = a0.x * r0.x + a0.y * r0.y + a0.z * r0.z + a0.w * r0.w
            + a1.x * r1.x + a1.y * r1.y + a1.z * r1.z + a1.w * r1.w;
#pragma unroll
    for (int o = 16; o; o >>= 1) s += __shfl_xor_sync(0xFFFFFFFFu, s, o);
    if (lane == 0) g_v[q * D + d] = s;
}

// --------------------------------------------------------------------------
// Kernel 3: per-sentence. One CTA per sentence; x tile (128 KB) staged in
// SMEM once, used for both word-attention dots and weighted pooling.
// --------------------------------------------------------------------------
#define SMEM_FLOATS (SEQ_L * D + D + SEQ_L + 16)
#define SMEM_BYTES  (SMEM_FLOATS * 4)

__global__ __launch_bounds__(256) void sent_kernel(
    const float* __restrict__ x, const int* __restrict__ aq) {
    extern __shared__ float sm[];
    float* xs  = sm;                 // [SEQ_L * D]
    float* vsh = sm + SEQ_L * D;     // [D]
    float* wgt = vsh + D;            // [SEQ_L]
    float* red = wgt + SEQ_L;        // [8]

    int n    = blockIdx.x;
    int tid  = threadIdx.x;
    int warp = tid >> 5;
    int lane = tid & 31;

    int q = aq[n * g_qstride];

    // stage v[q] and the x tile
    vsh[tid] = g_v[q * D + tid];
    const float4* xg  = (const float4*)(x + (size_t)n * (SEQ_L * D));
    float4*       xs4 = (float4*)xs;
#pragma unroll
    for (int i = 0; i < (SEQ_L * D / 4) / 256; i++)
        xs4[i * 256 + tid] = xg[i * 256 + tid];
    __syncthreads();

    // word-attention logits: warp per word, float4 smem reads (conflict-free)
    const float4* v4 = (const float4*)vsh;
    float4 va = v4[lane], vb = v4[lane + 32];
#pragma unroll
    for (int l = warp; l < SEQ_L; l += 8) {
        const float4* xr = (const float4*)(xs + l * D);
        float4 xa = xr[lane], xb = xr[lane + 32];
        float s = xa.x * va.x + xa.y * va.y + xa.z * va.z + xa.w * va.w
                + xb.x * vb.x + xb.y * vb.y + xb.z * vb.z + xb.w * vb.w;
#pragma unroll
        for (int o = 16; o; o >>= 1) s += __shfl_xor_sync(0xFFFFFFFFu, s, o);
        if (lane == 0) wgt[l] = s;
    }
    __syncthreads();

    // softmax over 128 words (warp 0, 4 values/lane)
    if (warp == 0) {
        float l0 = wgt[lane],      l1 = wgt[lane + 32];
        float l2 = wgt[lane + 64], l3 = wgt[lane + 96];
        float m = fmaxf(fmaxf(l0, l1), fmaxf(l2, l3));
#pragma unroll
        for (int o = 16; o; o >>= 1) m = fmaxf(m, __shfl_xor_sync(0xFFFFFFFFu, m, o));
        float e0 = __expf(l0 - m), e1 = __expf(l1 - m);
        float e2 = __expf(l2 - m), e3 = __expf(l3 - m);
        float s = e0 + e1 + e2 + e3;
#pragma unroll
        for (int o = 16; o; o >>= 1) s += __shfl_xor_sync(0xFFFFFFFFu, s, o);
        float inv = 1.0f / s;
        wgt[lane]      = e0 * inv; wgt[lane + 32] = e1 * inv;
        wgt[lane + 64] = e2 * inv; wgt[lane + 96] = e3 * inv;
    }
    __syncthreads();

    // pooled vector: thread tid owns dimension d = tid
    float acc = 0.0f;
#pragma unroll 8
    for (int l = 0; l < SEQ_L; l++)
        acc = fmaf(wgt[l], xs[l * D + tid], acc);
    g_xpool[n * D + tid] = acc;

    // bag-attention logit: block reduce of acc * u[q][d]
    float t = acc * g_u[q * D + tid];
#pragma unroll
    for (int o = 16; o; o >>= 1) t += __shfl_xor_sync(0xFFFFFFFFu, t, o);
    if (lane == 0) red[warp] = t;
    __syncthreads();
    if (tid == 0) {
        float s = 0.0f;
#pragma unroll
        for (int w = 0; w < 8; w++) s += red[w];
        g_logit[n] = s;
    }
}

// --------------------------------------------------------------------------
// Kernel 4: per-bag softmax over 16 sentences, weighted sum -> repre,
// then logits = repre @ relW^T + bias. One CTA per bag.
// (seg_ids are repeat(arange(NUM_BAGS), 16): contiguous bags.)
// --------------------------------------------------------------------------
__global__ __launch_bounds__(256) void bag_kernel(
    const float* __restrict__ relW, const float* __restrict__ bias,
    float* __restrict__ out) {
    __shared__ float wsh[BAG];
    __shared__ float repsh[D];

    int b    = blockIdx.x;
    int tid  = threadIdx.x;
    int warp = tid >> 5;
    int lane = tid & 31;

    if (warp == 0) {
        float lg = (lane < BAG) ? g_logit[b * BAG + lane] : -3.4e38f;
        float m = lg;
#pragma unroll
        for (int o = 16; o; o >>= 1) m = fmaxf(m, __shfl_xor_sync(0xFFFFFFFFu, m, o));
        float e = (lane < BAG) ? __expf(lg - m) : 0.0f;
        float s = e;
#pragma unroll
        for (int o = 16; o; o >>= 1) s += __shfl_xor_sync(0xFFFFFFFFu, s, o);
        if (lane < BAG) wsh[lane] = e / s;
    }
    __syncthreads();

    float rep = 0.0f;
#pragma unroll
    for (int i = 0; i < BAG; i++)
        rep = fmaf(wsh[i], g_xpool[(b * BAG + i) * D + tid], rep);
    repsh[tid] = rep;
    __syncthreads();

    // final logits: warp per class (8 classes per warp)
#pragma unroll
    for (int c = warp; c < C; c += 8) {
        const float* wr = relW + c * D;
        float s = 0.0f;
#pragma unroll
        for (int j = 0; j < 8; j++)
            s = fmaf(repsh[j * 32 + lane], wr[j * 32 + lane], s);
#pragma unroll
        for (int o = 16; o; o >>= 1) s += __shfl_xor_sync(0xFFFFFFFFu, s, o);
        if (lane == 0) out[b * C + c] = s + bias[c];
    }
}

// --------------------------------------------------------------------------
extern "C" void kernel_launch(void* const* d_in, const int* in_sizes, int n_in,
                              void* d_out, int out_size) {
    const float* x    = (const float*)d_in[0];
    const int*   aq   = (const int*)d_in[1];
    // d_in[2] = seg_ids (contiguous bags by construction; unused)
    const float* relW = (const float*)d_in[3];
    const float* attW = (const float*)d_in[4];
    const float* asmW = (const float*)d_in[5];
    const float* bias = (const float*)d_in[6];
    float*       out  = (float*)d_out;

    cudaFuncSetAttribute(sent_kernel,
                         cudaFuncAttributeMaxDynamicSharedMemorySize, SMEM_BYTES);

    detect_kernel<<<1, 256>>>(aq);
    pre_u_kernel<<<C, D>>>(relW, attW);
    pre_v_kernel<<<C * 32, 256>>>(asmW, relW);
    sent_kernel<<<N_SENT, 256, SMEM_BYTES>>>(x, aq);
    bag_kernel<<<NUM_BAGS, 256>>>(relW, bias, out);
}

// round 4
// speedup vs baseline: 1.7564x; 1.7564x over previous
#include <cuda_runtime.h>

#define N_SENT   2048
#define SEQ_L    128
#define D        256
#define C        64
#define NUM_BAGS 128
#define BAG      16
#define W        16              // words per chunk
#define NCHUNK   (SEQ_L / W)     // 8

// Scratch (device globals — no allocation allowed)
__device__ float g_v[C * D];          // v_q = A_q @ rq_q
__device__ float g_u[C * D];          // u_q = attW_q * relW_q
__device__ float g_xpool[N_SENT * D]; // per-sentence pooled vectors
__device__ float g_logit[N_SENT];    // per-sentence bag-attention logits
__device__ int   g_qstride;          // 1 if attention_query is int32, 2 if int64

// --------------------------------------------------------------------------
// Kernel 0: detect int32 vs int64 layout of attention_query (see R2 notes).
// --------------------------------------------------------------------------
__global__ void detect_kernel(const int* __restrict__ aq) {
    __shared__ int s_any;
    if (threadIdx.x == 0) s_any = 0;
    __syncthreads();
    int local = 0;
    for (int t = threadIdx.x; t < N_SENT / 2; t += blockDim.x)
        local |= aq[2 * t + 1];
    if (local) atomicOr(&s_any, 1);
    __syncthreads();
    if (threadIdx.x == 0) g_qstride = s_any ? 1 : 2;
}

// --------------------------------------------------------------------------
// Kernel 1: u_q[d] = attention_W[q][d] * relation_W[q][d]
// --------------------------------------------------------------------------
__global__ void pre_u_kernel(const float* __restrict__ relW,
                             const float* __restrict__ attW) {
    int i = blockIdx.x * D + threadIdx.x;
    g_u[i] = relW[i] * attW[i];
}

// --------------------------------------------------------------------------
// Kernel 2: v_q[d] = sum_e assemble_W[q][d*D + e] * relation_W[q][e]
// warp per output row, coalesced float4 reads of the 64 MiB assemble_W.
// --------------------------------------------------------------------------
__global__ __launch_bounds__(256) void pre_v_kernel(
    const float* __restrict__ asmW, const float* __restrict__ relW) {
    int b    = blockIdx.x;
    int q    = b >> 5;
    int warp = threadIdx.x >> 5;
    int lane = threadIdx.x & 31;
    int d    = ((b & 31) << 3) + warp;

    const float4* arow = (const float4*)(asmW + (size_t)q * (D * D) + (size_t)d * D);
    const float4* rq4  = (const float4*)(relW + q * D);

    float4 a0 = arow[lane],      a1 = arow[lane + 32];
    float4 r0 = rq4[lane],       r1 = rq4[lane + 32];
    float s = a0.x * r0.x + a0.y * r0.y + a0.z * r0.z + a0.w * r0.w
            + a1.x * r1.x + a1.y * r1.y + a1.z * r1.z + a1.w * r1.w;
#pragma unroll
    for (int o = 16; o; o >>= 1) s += __shfl_xor_sync(0xFFFFFFFFu, s, o);
    if (lane == 0) g_v[q * D + d] = s;
}

// --------------------------------------------------------------------------
// Kernel 3: per-sentence, online-softmax single pass over 16-word chunks.
// smem ~17.5 KB -> 8 CTAs/SM (thread-limited), full occupancy.
// --------------------------------------------------------------------------
__global__ __launch_bounds__(256) void sent_kernel(
    const float* __restrict__ x, const int* __restrict__ aq) {
    __shared__ float xs[W * D];      // 16 KB chunk
    __shared__ float vsh[D];
    __shared__ float lg[W];
    __shared__ float wsh[W];
    __shared__ float sm_m, sm_s, sm_f;
    __shared__ float red[8];

    int n    = blockIdx.x;
    int tid  = threadIdx.x;
    int warp = tid >> 5;
    int lane = tid & 31;

    int q = aq[n * g_qstride];
    vsh[tid] = g_v[q * D + tid];
    if (tid == 0) { sm_m = -3.4e38f; sm_s = 0.0f; }
    __syncthreads();

    const float4* v4 = (const float4*)vsh;
    float4 va = v4[lane], vb = v4[lane + 32];

    float acc = 0.0f;
    const float4* xg = (const float4*)(x + (size_t)n * (SEQ_L * D));

    for (int c = 0; c < NCHUNK; c++) {
        // stage chunk: 16 words x 256 dims = 1024 float4, 4 per thread
        float4*       xs4 = (float4*)xs;
        const float4* src = xg + c * (W * D / 4);
#pragma unroll
        for (int i = 0; i < 4; i++)
            xs4[i * 256 + tid] = src[i * 256 + tid];
        __syncthreads();

        // per-word logits: warp handles words 2*warp, 2*warp+1
#pragma unroll
        for (int j = 0; j < 2; j++) {
            int l = warp * 2 + j;
            const float4* xr = (const float4*)(xs + l * D);
            float4 xa = xr[lane], xb = xr[lane + 32];
            float s = xa.x * va.x + xa.y * va.y + xa.z * va.z + xa.w * va.w
                    + xb.x * vb.x + xb.y * vb.y + xb.z * vb.z + xb.w * vb.w;
#pragma unroll
            for (int o = 16; o; o >>= 1) s += __shfl_xor_sync(0xFFFFFFFFu, s, o);
            if (lane == 0) lg[l] = s;
        }
        __syncthreads();

        // online softmax state update (warp 0)
        if (warp == 0) {
            float lv = (lane < W) ? lg[lane] : -3.4e38f;
            float mc = lv;
#pragma unroll
            for (int o = 16; o; o >>= 1) mc = fmaxf(mc, __shfl_xor_sync(0xFFFFFFFFu, mc, o));
            float m_old = sm_m;
            float m_new = fmaxf(m_old, mc);
            float e = (lane < W) ? __expf(lv - m_new) : 0.0f;
            float ssum = e;
#pragma unroll
            for (int o = 16; o; o >>= 1) ssum += __shfl_xor_sync(0xFFFFFFFFu, ssum, o);
            if (lane < W) wsh[lane] = e;
            if (lane == 0) {
                float f = __expf(m_old - m_new);   // 0 on first chunk
                sm_s = sm_s * f + ssum;
                sm_m = m_new;
                sm_f = f;
            }
        }
        __syncthreads();

        // rescale + weighted accumulate (thread owns d = tid)
        float f = sm_f;
        acc *= f;
#pragma unroll
        for (int l = 0; l < W; l++)
            acc = fmaf(wsh[l], xs[l * D + tid], acc);
        __syncthreads();   // protect xs/wsh before next chunk overwrites
    }

    float xp = acc / sm_s;
    g_xpool[n * D + tid] = xp;

    // bag-attention logit: block reduce of xp * u[q][d]
    float t = xp * g_u[q * D + tid];
#pragma unroll
    for (int o = 16; o; o >>= 1) t += __shfl_xor_sync(0xFFFFFFFFu, t, o);
    if (lane == 0) red[warp] = t;
    __syncthreads();
    if (tid == 0) {
        float s = 0.0f;
#pragma unroll
        for (int w = 0; w < 8; w++) s += red[w];
        g_logit[n] = s;
    }
}

// --------------------------------------------------------------------------
// Kernel 4: per-bag softmax over 16 sentences, weighted sum -> repre,
// then logits = repre @ relW^T + bias. One CTA per bag.
// --------------------------------------------------------------------------
__global__ __launch_bounds__(256) void bag_kernel(
    const float* __restrict__ relW, const float* __restrict__ bias,
    float* __restrict__ out) {
    __shared__ float wsh[BAG];
    __shared__ float repsh[D];

    int b    = blockIdx.x;
    int tid  = threadIdx.x;
    int warp = tid >> 5;
    int lane = tid & 31;

    if (warp == 0) {
        float lgv = (lane < BAG) ? g_logit[b * BAG + lane] : -3.4e38f;
        float m = lgv;
#pragma unroll
        for (int o = 16; o; o >>= 1) m = fmaxf(m, __shfl_xor_sync(0xFFFFFFFFu, m, o));
        float e = (lane < BAG) ? __expf(lgv - m) : 0.0f;
        float s = e;
#pragma unroll
        for (int o = 16; o; o >>= 1) s += __shfl_xor_sync(0xFFFFFFFFu, s, o);
        if (lane < BAG) wsh[lane] = e / s;
    }
    __syncthreads();

    float rep = 0.0f;
#pragma unroll
    for (int i = 0; i < BAG; i++)
        rep = fmaf(wsh[i], g_xpool[(b * BAG + i) * D + tid], rep);
    repsh[tid] = rep;
    __syncthreads();

#pragma unroll
    for (int c = warp; c < C; c += 8) {
        const float* wr = relW + c * D;
        float s = 0.0f;
#pragma unroll
        for (int j = 0; j < 8; j++)
            s = fmaf(repsh[j * 32 + lane], wr[j * 32 + lane], s);
#pragma unroll
        for (int o = 16; o; o >>= 1) s += __shfl_xor_sync(0xFFFFFFFFu, s, o);
        if (lane == 0) out[b * C + c] = s + bias[c];
    }
}

// --------------------------------------------------------------------------
extern "C" void kernel_launch(void* const* d_in, const int* in_sizes, int n_in,
                              void* d_out, int out_size) {
    const float* x    = (const float*)d_in[0];
    const int*   aq   = (const int*)d_in[1];
    // d_in[2] = seg_ids (contiguous bags by construction; unused)
    const float* relW = (const float*)d_in[3];
    const float* attW = (const float*)d_in[4];
    const float* asmW = (const float*)d_in[5];
    const float* bias = (const float*)d_in[6];
    float*       out  = (float*)d_out;

    detect_kernel<<<1, 256>>>(aq);
    pre_u_kernel<<<C, D>>>(relW, attW);
    pre_v_kernel<<<C * 32, 256>>>(asmW, relW);
    sent_kernel<<<N_SENT, 256>>>(x, aq);
    bag_kernel<<<NUM_BAGS, 256>>>(relW, bias, out);
}

// round 10
// speedup vs baseline: 2.1024x; 1.1970x over previous
#include <cuda_runtime.h>
#include <cstdint>

#define N_SENT   2048
#define SEQ_L    128
#define D        256
#define C        64
#define NUM_BAGS 128
#define BAG      16
#define W        8               // words per chunk
#define NCHUNK   (SEQ_L / W)     // 16
#define CH_F4    (W * D / 4)     // 512 float4 per chunk

// Scratch (device globals — no allocation allowed)
__device__ float g_v[C * D];          // v_q = A_q @ rq_q
__device__ float g_u[C * D];          // u_q = attW_q * relW_q
__device__ float g_xpool[N_SENT * D]; // per-sentence pooled vectors
__device__ float g_logit[N_SENT];    // per-sentence bag-attention logits
__device__ int   g_qstride;          // 1 if attention_query is int32, 2 if int64

// --------------------------------------------------------------------------
// Kernel 0: detect int32 vs int64 layout of attention_query.
// int64 (values 0..63, little-endian) => every odd 32-bit word is zero.
// --------------------------------------------------------------------------
__global__ void detect_kernel(const int* __restrict__ aq) {
    __shared__ int s_any;
    if (threadIdx.x == 0) s_any = 0;
    __syncthreads();
    int local = 0;
    for (int t = threadIdx.x; t < N_SENT / 2; t += blockDim.x)
        local |= aq[2 * t + 1];
    if (local) atomicOr(&s_any, 1);
    __syncthreads();
    if (threadIdx.x == 0) g_qstride = s_any ? 1 : 2;
}

// --------------------------------------------------------------------------
// Kernel 1: u_q[d] = attention_W[q][d] * relation_W[q][d]
// --------------------------------------------------------------------------
__global__ void pre_u_kernel(const float* __restrict__ relW,
                             const float* __restrict__ attW) {
    int i = blockIdx.x * D + threadIdx.x;
    g_u[i] = relW[i] * attW[i];
}

// --------------------------------------------------------------------------
// Kernel 2: v_q[d] = sum_e assemble_W[q][d*D + e] * relation_W[q][e]
// warp per output row, coalesced float4 reads of the 64 MiB assemble_W.
// --------------------------------------------------------------------------
__global__ __launch_bounds__(256) void pre_v_kernel(
    const float* __restrict__ asmW, const float* __restrict__ relW) {
    int b    = blockIdx.x;
    int q    = b >> 5;
    int warp = threadIdx.x >> 5;
    int lane = threadIdx.x & 31;
    int d    = ((b & 31) << 3) + warp;

    const float4* arow = (const float4*)(asmW + (size_t)q * (D * D) + (size_t)d * D);
    const float4* rq4  = (const float4*)(relW + q * D);

    float4 a0 = arow[lane],      a1 = arow[lane + 32];
    float4 r0 = rq4[lane],       r1 = rq4[lane + 32];
    float s = a0.x * r0.x + a0.y * r0.y + a0.z * r0.z + a0.w * r0.w
            + a1.x * r1.x + a1.y * r1.y + a1.z * r1.z + a1.w * r1.w;
#pragma unroll
    for (int o = 16; o; o >>= 1) s += __shfl_xor_sync(0xFFFFFFFFu, s, o);
    if (lane == 0) g_v[q * D + d] = s;
}

// --------------------------------------------------------------------------
// Kernel 3: per-sentence, cp.async double-buffered stream + warp-private
// online softmax (flash-decoding split over words), one 8-way merge at end.
// --------------------------------------------------------------------------
__device__ __forceinline__ void cp16(uint32_t dst, const void* src) {
    asm volatile("cp.async.cg.shared.global [%0], [%1], 16;\n"
                 :: "r"(dst), "l"(src));
}
__device__ __forceinline__ void cp_commit() {
    asm volatile("cp.async.commit_group;\n");
}

__global__ __launch_bounds__(256) void sent_kernel(
    const float* __restrict__ x, const int* __restrict__ aq) {
    __shared__ float buf0[W * D];     // 8 KB
    __shared__ float buf1[W * D];     // 8 KB
    __shared__ float mrg[8 * D];      // 8 KB merge scratch
    __shared__ float m_sm[8], s_sm[8], red[8];

    int n    = blockIdx.x;
    int tid  = threadIdx.x;
    int warp = tid >> 5;
    int lane = tid & 31;

    const float4* xg = (const float4*)(x + (size_t)n * (SEQ_L * D));
    uint32_t b0 = (uint32_t)__cvta_generic_to_shared(buf0);
    uint32_t b1 = (uint32_t)__cvta_generic_to_shared(buf1);

    // prologue: stage chunks 0 and 1
    {
        const float4* s0 = xg;
        cp16(b0 + tid * 16, s0 + tid);
        cp16(b0 + (tid + 256) * 16, s0 + tid + 256);
        cp_commit();
        const float4* s1 = xg + CH_F4;
        cp16(b1 + tid * 16, s1 + tid);
        cp16(b1 + (tid + 256) * 16, s1 + tid + 256);
        cp_commit();
    }

    int q = aq[n * g_qstride];
    const float4* vg = (const float4*)(g_v + q * D);
    float4 v0 = vg[2 * lane], v1 = vg[2 * lane + 1];

    float m_w = -3.4e38f, s_w = 0.0f;
    float acc[8];
#pragma unroll
    for (int j = 0; j < 8; j++) acc[j] = 0.0f;

    for (int c = 0; c < NCHUNK; c++) {
        asm volatile("cp.async.wait_group 1;\n");
        __syncthreads();                       // chunk c visible to all

        const float* buf = (c & 1) ? buf1 : buf0;
        const float4* xr = (const float4*)(buf + warp * D);  // warp's word
        float4 a0 = xr[2 * lane], a1 = xr[2 * lane + 1];

        float p = a0.x * v0.x + a0.y * v0.y + a0.z * v0.z + a0.w * v0.w
                + a1.x * v1.x + a1.y * v1.y + a1.z * v1.z + a1.w * v1.w;
#pragma unroll
        for (int o = 16; o; o >>= 1) p += __shfl_xor_sync(0xFFFFFFFFu, p, o);

        float m_new = fmaxf(m_w, p);
        float e = __expf(p - m_new);
        float f = __expf(m_w - m_new);         // 0 on first chunk
        s_w = s_w * f + e;
        m_w = m_new;
        acc[0] = acc[0] * f + e * a0.x;  acc[1] = acc[1] * f + e * a0.y;
        acc[2] = acc[2] * f + e * a0.z;  acc[3] = acc[3] * f + e * a0.w;
        acc[4] = acc[4] * f + e * a1.x;  acc[5] = acc[5] * f + e * a1.y;
        acc[6] = acc[6] * f + e * a1.z;  acc[7] = acc[7] * f + e * a1.w;

        __syncthreads();                       // all warps done with buf[c&1]
        if (c + 2 < NCHUNK) {
            uint32_t db = (c & 1) ? b1 : b0;
            const float4* src = xg + (size_t)(c + 2) * CH_F4;
            cp16(db + tid * 16, src + tid);
            cp16(db + (tid + 256) * 16, src + tid + 256);
        }
        cp_commit();                           // one group per iteration
    }

    // 8-way warp merge: lane owns dims [lane*8, lane*8+8)
    float4 o0 = make_float4(acc[0], acc[1], acc[2], acc[3]);
    float4 o1 = make_float4(acc[4], acc[5], acc[6], acc[7]);
    float4* mw = (float4*)(mrg + warp * D);
    mw[2 * lane] = o0;  mw[2 * lane + 1] = o1;
    if (lane == 0) { m_sm[warp] = m_w; s_sm[warp] = s_w; }
    __syncthreads();

    float mst = -3.4e38f;
#pragma unroll
    for (int w = 0; w < 8; w++) mst = fmaxf(mst, m_sm[w]);
    float den = 0.0f, num = 0.0f;
#pragma unroll
    for (int w = 0; w < 8; w++) {
        float fw = __expf(m_sm[w] - mst);
        den = fmaf(fw, s_sm[w], den);
        num = fmaf(fw, mrg[w * D + tid], num);
    }
    float xp = num / den;
    g_xpool[n * D + tid] = xp;

    // bag-attention logit: block reduce of xp * u[q][d]
    float t = xp * g_u[q * D + tid];
#pragma unroll
    for (int o = 16; o; o >>= 1) t += __shfl_xor_sync(0xFFFFFFFFu, t, o);
    if (lane == 0) red[warp] = t;
    __syncthreads();
    if (tid == 0) {
        float s = 0.0f;
#pragma unroll
        for (int w = 0; w < 8; w++) s += red[w];
        g_logit[n] = s;
    }
}

// --------------------------------------------------------------------------
// Kernel 4: per-bag softmax over 16 sentences, weighted sum -> repre,
// then logits = repre @ relW^T + bias. One CTA per bag.
// --------------------------------------------------------------------------
__global__ __launch_bounds__(256) void bag_kernel(
    const float* __restrict__ relW, const float* __restrict__ bias,
    float* __restrict__ out) {
    __shared__ float wsh[BAG];
    __shared__ float repsh[D];

    int b    = blockIdx.x;
    int tid  = threadIdx.x;
    int warp = tid >> 5;
    int lane = tid & 31;

    if (warp == 0) {
        float lgv = (lane < BAG) ? g_logit[b * BAG + lane] : -3.4e38f;
        float m = lgv;
#pragma unroll
        for (int o = 16; o; o >>= 1) m = fmaxf(m, __shfl_xor_sync(0xFFFFFFFFu, m, o));
        float e = (lane < BAG) ? __expf(lgv - m) : 0.0f;
        float s = e;
#pragma unroll
        for (int o = 16; o; o >>= 1) s += __shfl_xor_sync(0xFFFFFFFFu, s, o);
        if (lane < BAG) wsh[lane] = e / s;
    }
    __syncthreads();

    float rep = 0.0f;
#pragma unroll
    for (int i = 0; i < BAG; i++)
        rep = fmaf(wsh[i], g_xpool[(b * BAG + i) * D + tid], rep);
    repsh[tid] = rep;
    __syncthreads();

#pragma unroll
    for (int c = warp; c < C; c += 8) {
        const float* wr = relW + c * D;
        float s = 0.0f;
#pragma unroll
        for (int j = 0; j < 8; j++)
            s = fmaf(repsh[j * 32 + lane], wr[j * 32 + lane], s);
#pragma unroll
        for (int o = 16; o; o >>= 1) s += __shfl_xor_sync(0xFFFFFFFFu, s, o);
        if (lane == 0) out[b * C + c] = s + bias[c];
    }
}

// --------------------------------------------------------------------------
extern "C" void kernel_launch(void* const* d_in, const int* in_sizes, int n_in,
                              void* d_out, int out_size) {
    const float* x    = (const float*)d_in[0];
    const int*   aq   = (const int*)d_in[1];
    // d_in[2] = seg_ids (contiguous bags by construction; unused)
    const float* relW = (const float*)d_in[3];
    const float* attW = (const float*)d_in[4];
    const float* asmW = (const float*)d_in[5];
    const float* bias = (const float*)d_in[6];
    float*       out  = (float*)d_out;

    detect_kernel<<<1, 256>>>(aq);
    pre_u_kernel<<<C, D>>>(relW, attW);
    pre_v_kernel<<<C * 32, 256>>>(asmW, relW);
    sent_kernel<<<N_SENT, 256>>>(x, aq);
    bag_kernel<<<NUM_BAGS, 256>>>(relW, bias, out);
}

// round 12
// speedup vs baseline: 2.4725x; 1.1760x over previous
#include <cuda_runtime.h>
#include <cstdint>

#define N_SENT   2048
#define SEQ_L    128
#define D        256
#define C        64
#define NUM_BAGS 128
#define BAG      16

// Scratch (device globals — no allocation allowed)
__device__ float g_v[C * D];          // v_q = A_q @ rq_q
__device__ float g_u[C * D];          // u_q = attW_q * relW_q
__device__ float g_xpool[N_SENT * D]; // per-sentence pooled vectors
__device__ float g_logit[N_SENT];    // per-sentence bag-attention logits
__device__ int   g_qstride;          // 1 if attention_query is int32, 2 if int64

__device__ __forceinline__ void cp16(uint32_t dst, const void* src) {
    asm volatile("cp.async.cg.shared.global [%0], [%1], 16;\n"
                 :: "r"(dst), "l"(src));
}
__device__ __forceinline__ void cp_commit() {
    asm volatile("cp.async.commit_group;\n");
}
__device__ __forceinline__ float dot4(float4 a, float4 b) {
    return a.x * b.x + a.y * b.y + a.z * b.z + a.w * b.w;
}

// --------------------------------------------------------------------------
// Fused pre-kernel:
//   blocks [0,1024)    : v_q[d] = A_q[d,:] . rq_q   (2 rows/warp, MLP=4)
//   blocks [1024,1088) : u_q[d] = attW*relW
//   block  1088        : int32/int64 detect of attention_query
// --------------------------------------------------------------------------
__global__ __launch_bounds__(256) void pre_kernel(
    const float* __restrict__ asmW, const float* __restrict__ relW,
    const float* __restrict__ attW, const int* __restrict__ aq) {
    __shared__ int s_any;
    int b = blockIdx.x;

    if (b < 1024) {
        int q    = b >> 4;
        int warp = threadIdx.x >> 5;
        int lane = threadIdx.x & 31;
        int d0   = ((b & 15) << 4) + (warp << 1);   // 2 rows per warp

        const float4* a0p = (const float4*)(asmW + (size_t)q * (D * D) + (size_t)d0 * D);
        const float4* a1p = a0p + (D / 4);
        const float4* rq4 = (const float4*)(relW + q * D);

        float4 x0 = a0p[lane], x1 = a0p[lane + 32];
        float4 y0 = a1p[lane], y1 = a1p[lane + 32];
        float4 r0 = rq4[lane], r1 = rq4[lane + 32];

        float s0 = dot4(x0, r0) + dot4(x1, r1);
        float s1 = dot4(y0, r0) + dot4(y1, r1);
#pragma unroll
        for (int o = 16; o; o >>= 1) {
            s0 += __shfl_xor_sync(0xFFFFFFFFu, s0, o);
            s1 += __shfl_xor_sync(0xFFFFFFFFu, s1, o);
        }
        if (lane == 0) {
            g_v[q * D + d0]     = s0;
            g_v[q * D + d0 + 1] = s1;
        }
    } else if (b < 1088) {
        int q = b - 1024;
        int i = q * D + threadIdx.x;
        g_u[i] = relW[i] * attW[i];
    } else {
        if (threadIdx.x == 0) s_any = 0;
        __syncthreads();
        int local = 0;
        for (int t = threadIdx.x; t < N_SENT / 2; t += blockDim.x)
            local |= aq[2 * t + 1];
        if (local) atomicOr(&s_any, 1);
        __syncthreads();
        if (threadIdx.x == 0) g_qstride = s_any ? 1 : 2;
    }
}

// --------------------------------------------------------------------------
// Sentence kernel: warp-autonomous streaming. Warp w owns words w+8k
// (k=0..15) with a private 3-slot cp.async ring (1 KB/word). Each lane
// copies and later reads exactly its own bytes (float4 slots lane and
// lane+32), so per-thread cp.async.wait_group is the only sync in the loop
// — no block or warp barriers until the final 8-way merge.
// --------------------------------------------------------------------------
__global__ __launch_bounds__(256) void sent_kernel(
    const float* __restrict__ x, const int* __restrict__ aq) {
    __shared__ float sbuf[8 * 3 * 256];   // 24 KB: 8 warps x 3 slots x 1 KB
    __shared__ float m_sm[8], s_sm[8], red[8];

    int n    = blockIdx.x;
    int tid  = threadIdx.x;
    int warp = tid >> 5;
    int lane = tid & 31;

    int q = aq[n * g_qstride];
    const float4* vg = (const float4*)(g_v + q * D);
    float4 v0 = vg[lane], v1 = vg[lane + 32];   // dims 4L.. and 128+4L..

    const float* xw = x + (size_t)n * (SEQ_L * D) + warp * D;  // word warp+8k at +k*8*D
    float*   wsl = sbuf + warp * 768;
    uint32_t sb  = (uint32_t)__cvta_generic_to_shared(wsl);

    // prologue: words k=0,1 into slots 0,1
#pragma unroll
    for (int k = 0; k < 2; k++) {
        const float4* src = (const float4*)(xw + k * (8 * D));
        cp16(sb + k * 1024 + lane * 16,        src + lane);
        cp16(sb + k * 1024 + (lane + 32) * 16, src + lane + 32);
        cp_commit();
    }

    float m_w = -3.4e38f, s_w = 0.0f;
    float acc[8];
#pragma unroll
    for (int j = 0; j < 8; j++) acc[j] = 0.0f;

#pragma unroll
    for (int k = 0; k < 16; k++) {
        asm volatile("cp.async.wait_group 1;\n");   // word k resident (own bytes)

        const float4* xr = (const float4*)(wsl + (k % 3) * 256);
        float4 a0 = xr[lane], a1 = xr[lane + 32];

        float p = dot4(a0, v0) + dot4(a1, v1);
#pragma unroll
        for (int o = 16; o; o >>= 1) p += __shfl_xor_sync(0xFFFFFFFFu, p, o);

        float m_new = fmaxf(m_w, p);
        float e = __expf(p - m_new);
        float f = __expf(m_w - m_new);              // 0 on first word
        s_w = s_w * f + e;
        m_w = m_new;
        acc[0] = acc[0] * f + e * a0.x;  acc[1] = acc[1] * f + e * a0.y;
        acc[2] = acc[2] * f + e * a0.z;  acc[3] = acc[3] * f + e * a0.w;
        acc[4] = acc[4] * f + e * a1.x;  acc[5] = acc[5] * f + e * a1.y;
        acc[6] = acc[6] * f + e * a1.z;  acc[7] = acc[7] * f + e * a1.w;

        if (k + 2 < 16) {
            int ds = (k + 2) % 3;
            const float4* src = (const float4*)(xw + (k + 2) * (8 * D));
            cp16(sb + ds * 1024 + lane * 16,        src + lane);
            cp16(sb + ds * 1024 + (lane + 32) * 16, src + lane + 32);
        }
        cp_commit();                                // one group per iteration
    }

    // 8-way merge: reuse sbuf as [8][D] scratch (all cp.async retired first)
    asm volatile("cp.async.wait_group 0;\n");
    __syncthreads();
    float4* mw = (float4*)(sbuf + warp * D);
    mw[lane]      = make_float4(acc[0], acc[1], acc[2], acc[3]);  // dims 4L..
    mw[lane + 32] = make_float4(acc[4], acc[5], acc[6], acc[7]);  // dims 128+4L..
    if (lane == 0) { m_sm[warp] = m_w; s_sm[warp] = s_w; }
    __syncthreads();

    float mst = -3.4e38f;
#pragma unroll
    for (int w = 0; w < 8; w++) mst = fmaxf(mst, m_sm[w]);
    float den = 0.0f, num = 0.0f;
#pragma unroll
    for (int w = 0; w < 8; w++) {
        float fw = __expf(m_sm[w] - mst);
        den = fmaf(fw, s_sm[w], den);
        num = fmaf(fw, sbuf[w * D + tid], num);
    }
    float xp = num / den;
    g_xpool[n * D + tid] = xp;

    // bag-attention logit: block reduce of xp * u[q][d]
    float t = xp * g_u[q * D + tid];
#pragma unroll
    for (int o = 16; o; o >>= 1) t += __shfl_xor_sync(0xFFFFFFFFu, t, o);
    if (lane == 0) red[warp] = t;
    __syncthreads();
    if (tid == 0) {
        float s = 0.0f;
#pragma unroll
        for (int w = 0; w < 8; w++) s += red[w];
        g_logit[n] = s;
    }
}

// --------------------------------------------------------------------------
// Bag kernel: per-bag softmax over 16 sentences, weighted sum -> repre,
// then logits = repre @ relW^T + bias. One CTA per bag.
// --------------------------------------------------------------------------
__global__ __launch_bounds__(256) void bag_kernel(
    const float* __restrict__ relW, const float* __restrict__ bias,
    float* __restrict__ out) {
    __shared__ float wsh[BAG];
    __shared__ float repsh[D];

    int b    = blockIdx.x;
    int tid  = threadIdx.x;
    int warp = tid >> 5;
    int lane = tid & 31;

    if (warp == 0) {
        float lgv = (lane < BAG) ? g_logit[b * BAG + lane] : -3.4e38f;
        float m = lgv;
#pragma unroll
        for (int o = 16; o; o >>= 1) m = fmaxf(m, __shfl_xor_sync(0xFFFFFFFFu, m, o));
        float e = (lane < BAG) ? __expf(lgv - m) : 0.0f;
        float s = e;
#pragma unroll
        for (int o = 16; o; o >>= 1) s += __shfl_xor_sync(0xFFFFFFFFu, s, o);
        if (lane < BAG) wsh[lane] = e / s;
    }
    __syncthreads();

    float rep = 0.0f;
#pragma unroll
    for (int i = 0; i < BAG; i++)
        rep = fmaf(wsh[i], g_xpool[(b * BAG + i) * D + tid], rep);
    repsh[tid] = rep;
    __syncthreads();

#pragma unroll
    for (int c = warp; c < C; c += 8) {
        const float* wr = relW + c * D;
        float s = 0.0f;
#pragma unroll
        for (int j = 0; j < 8; j++)
            s = fmaf(repsh[j * 32 + lane], wr[j * 32 + lane], s);
#pragma unroll
        for (int o = 16; o; o >>= 1) s += __shfl_xor_sync(0xFFFFFFFFu, s, o);
        if (lane == 0) out[b * C + c] = s + bias[c];
    }
}

// --------------------------------------------------------------------------
extern "C" void kernel_launch(void* const* d_in, const int* in_sizes, int n_in,
                              void* d_out, int out_size) {
    const float* x    = (const float*)d_in[0];
    const int*   aq   = (const int*)d_in[1];
    // d_in[2] = seg_ids (contiguous bags by construction; unused)
    const float* relW = (const float*)d_in[3];
    const float* attW = (const float*)d_in[4];
    const float* asmW = (const float*)d_in[5];
    const float* bias = (const float*)d_in[6];
    float*       out  = (float*)d_out;

    pre_kernel<<<1089, 256>>>(asmW, relW, attW, aq);
    sent_kernel<<<N_SENT, 256>>>(x, aq);
    bag_kernel<<<NUM_BAGS, 256>>>(relW, bias, out);
}